// round 7
// baseline (speedup 1.0000x reference)
#include <cuda_runtime.h>
#include <cstdint>

#define H_ 512
#define W_ 512
#define G_ 83
#define KK 12
#define NB 8
#define NV (G_ * G_)                 // 6889 vertices
#define NF (2 * (G_ - 1) * (G_ - 1)) // 13448 faces
#define HW (H_ * W_)

// 16 MB z-buffer scratch. Zero-initialized at module load; stores ~packed so
// that "empty" == 0 and atomicMax == lexicographic (depth, index) min.
// Shade resets every slot to 0 after consuming it, keeping replays clean.
__device__ unsigned long long g_zbuf[NB * HW];

// Strict IEEE, non-fused edge function: (a-b)*(c-d) - (e-f)*(g-h)
__device__ __forceinline__ float edgefn(float a, float b, float c, float d,
                                        float e, float f, float g, float h) {
    float t1 = __fmul_rn(__fsub_rn(a, b), __fsub_rn(c, d));
    float t2 = __fmul_rn(__fsub_rn(e, f), __fsub_rn(g, h));
    return __fsub_rn(t1, t2);
}

// One warp per (batch, triangle). Lanes split the candidate window rows.
__global__ void raster_kernel(const float* __restrict__ verts,
                              const int* __restrict__ faces) {
    int gw = (blockIdx.x * blockDim.x + threadIdx.x) >> 5;
    int lane = threadIdx.x & 31;
    if (gw >= NB * NF) return;
    int n = gw / NF;
    int f = gw - n * NF;

    int i0 = faces[3 * f + 0];
    int i1 = faces[3 * f + 1];
    int i2 = faces[3 * f + 2];
    const float* vb = verts + (size_t)n * NV * 3;

    float z0 = vb[3 * i0 + 2], z1 = vb[3 * i1 + 2], z2 = vb[3 * i2 + 2];
    // p = v * (1/z); rcp.rn is correctly rounded == div.rn(1,z) bitwise.
    float r0 = __frcp_rn(z0), r1 = __frcp_rn(z1), r2 = __frcp_rn(z2);
    float x0 = __fmul_rn(vb[3 * i0 + 0], r0), y0 = __fmul_rn(vb[3 * i0 + 1], r0);
    float x1 = __fmul_rn(vb[3 * i1 + 0], r1), y1 = __fmul_rn(vb[3 * i1 + 1], r1);
    float x2 = __fmul_rn(vb[3 * i2 + 0], r2), y2 = __fmul_rn(vb[3 * i2 + 1], r2);

    float area = edgefn(x1, x0, y2, y0, y1, y0, x2, x0);
    bool front = (z0 > 0.f) && (z1 > 0.f) && (z2 > 0.f);
    if (!front || !(fabsf(area) > 1e-9f)) return;
    float invA = __frcp_rn(area);

    float xmn = fminf(x0, fminf(x1, x2));
    float ymn = fminf(y0, fminf(y1, y2));
    float ymx = fmaxf(y0, fmaxf(y1, y2));
    int bcx = (int)fminf(fmaxf(floorf(xmn), 0.f), (float)(W_ - KK));
    int bcy = (int)fminf(fmaxf(floorf(ymn), 0.f), (float)(H_ - KK));

    // Row clip: pixels outside [floor(ymin), ceil(ymax)] are >= 1 px beyond the
    // vertex extent -> a barycentric is <= -0.1 exactly; fp noise can't flip it.
    int rowLo = max(bcy, (int)floorf(ymn));
    int rowHi = min(bcy + KK - 1, (int)ceilf(ymx));
    int tBeg = (rowLo - bcy) * KK;
    int tEnd = (rowHi - bcy + 1) * KK;

    unsigned long long* zb = g_zbuf + (size_t)n * HW;
    int mbase = f * (KK * KK);

    for (int t = tBeg + lane; t < tEnd; t += 32) {
        int oy = t / KK;          // const divisor -> mul/shift
        int ox = t - oy * KK;
        int px = bcx + ox;
        int py = bcy + oy;
        float pxf = (float)px, pyf = (float)py;
        float w0 = __fmul_rn(edgefn(x2, x1, pyf, y1, y2, y1, pxf, x1), invA);
        float w1 = __fmul_rn(edgefn(x0, x2, pyf, y2, y0, y2, pxf, x2), invA);
        float w2 = __fsub_rn(__fsub_rn(1.0f, w0), w1);
        if (w0 >= 0.f && w1 >= 0.f && w2 >= 0.f) {
            float depth = __fadd_rn(
                __fadd_rn(__fmul_rn(w0, z0), __fmul_rn(w1, z1)),
                __fmul_rn(w2, z2));
            unsigned long long packed =
                ((unsigned long long)__float_as_uint(depth) << 32) |
                (unsigned int)(mbase + t);
            atomicMax(zb + py * W_ + px, ~packed);   // max(~x) == ~min(x)
        }
    }
}

// One thread per (batch, pixel): decode winner, recompute barycentrics with the
// SAME arithmetic, interpolate uv, apply epilogue, write uvs + mask, reset zbuf.
__global__ void shade_kernel(const float* __restrict__ verts,
                             const int* __restrict__ faces,
                             const float* __restrict__ vals,
                             float* __restrict__ out) {
    int gid = blockIdx.x * blockDim.x + threadIdx.x;
    if (gid >= NB * HW) return;
    int n = gid / HW;
    int pix = gid - n * HW;

    unsigned long long zv = g_zbuf[gid];
    g_zbuf[gid] = 0ull;   // reset for next replay (empty state == 0)

    float u = 0.f, v = 0.f;
    if (zv != 0ull) {
        unsigned long long packed = ~zv;
        int m = (int)(unsigned int)(packed & 0xFFFFFFFFu);
        int f = m / (KK * KK);
        int i0 = faces[3 * f + 0];
        int i1 = faces[3 * f + 1];
        int i2 = faces[3 * f + 2];
        const float* vb = verts + (size_t)n * NV * 3;
        float z0 = vb[3 * i0 + 2], z1 = vb[3 * i1 + 2], z2 = vb[3 * i2 + 2];
        float r0 = __frcp_rn(z0), r1 = __frcp_rn(z1), r2 = __frcp_rn(z2);
        float x0 = __fmul_rn(vb[3 * i0 + 0], r0), y0 = __fmul_rn(vb[3 * i0 + 1], r0);
        float x1 = __fmul_rn(vb[3 * i1 + 0], r1), y1 = __fmul_rn(vb[3 * i1 + 1], r1);
        float x2 = __fmul_rn(vb[3 * i2 + 0], r2), y2 = __fmul_rn(vb[3 * i2 + 1], r2);
        float area = edgefn(x1, x0, y2, y0, y1, y0, x2, x0);
        float invA = __frcp_rn(area);
        int px = pix & (W_ - 1);
        int py = pix >> 9;
        float pxf = (float)px, pyf = (float)py;
        float w0 = __fmul_rn(edgefn(x2, x1, pyf, y1, y2, y1, pxf, x1), invA);
        float w1 = __fmul_rn(edgefn(x0, x2, pyf, y2, y0, y2, pxf, x2), invA);
        float w2 = __fsub_rn(__fsub_rn(1.0f, w0), w1);
        u = __fadd_rn(
            __fadd_rn(__fmul_rn(w0, vals[2 * i0 + 0]), __fmul_rn(w1, vals[2 * i1 + 0])),
            __fmul_rn(w2, vals[2 * i2 + 0]));
        v = __fadd_rn(
            __fadd_rn(__fmul_rn(w0, vals[2 * i0 + 1]), __fmul_rn(w1, vals[2 * i1 + 1])),
            __fmul_rn(w2, vals[2 * i2 + 1]));
    }
    float mask = (u > 0.f || v > 0.f) ? 1.f : 0.f;
    float ou, ov;
    if (mask > 0.f) {
        ou = __fsub_rn(__fmul_rn(2.f, u), 1.f);
        ov = __fsub_rn(__fmul_rn(2.f, v), 1.f);
    } else {
        ou = -10.f;
        ov = -10.f;
    }
    out[((size_t)n * 2 + 0) * HW + pix] = ou;
    out[((size_t)n * 2 + 1) * HW + pix] = ov;
    out[(size_t)NB * 2 * HW + (size_t)n * HW + pix] = mask;
}

extern "C" void kernel_launch(void* const* d_in, const int* in_sizes, int n_in,
                              void* d_out, int out_size) {
    const float* verts = (const float*)d_in[0];
    const int* faces = (const int*)d_in[1];
    const float* vals = (const float*)d_in[2];
    float* out = (float*)d_out;

    (void)in_sizes; (void)n_in; (void)out_size;

    int nwarps = NB * NF;                 // 107584 warps
    int rasterBlocks = (nwarps * 32 + 255) / 256;
    raster_kernel<<<rasterBlocks, 256>>>(verts, faces);

    int shadeBlocks = (NB * HW + 255) / 256;
    shade_kernel<<<shadeBlocks, 256>>>(verts, faces, vals, out);
}

// round 9
// speedup vs baseline: 1.0283x; 1.0283x over previous
#include <cuda_runtime.h>
#include <cstdint>

#define H_ 512
#define W_ 512
#define G_ 83
#define KK 12
#define NB 8
#define NV (G_ * G_)                 // 6889 vertices
#define NF (2 * (G_ - 1) * (G_ - 1)) // 13448 faces
#define HW (H_ * W_)

// 16 MB z-buffer scratch. Zero-initialized at module load; raster stores
// ~packed via atomicMax so "empty" == 0 and max(~x) == ~min(x) preserves the
// exact lexicographic (depth, face) minimum. Shade resets each slot to 0
// after consuming it, keeping graph replays clean without an init kernel.
__device__ unsigned long long g_zbuf[NB * HW];

// Strict IEEE, non-fused edge function: (a-b)*(c-d) - (e-f)*(g-h)
__device__ __forceinline__ float edgefn(float a, float b, float c, float d,
                                        float e, float f, float g, float h) {
    float t1 = __fmul_rn(__fsub_rn(a, b), __fsub_rn(c, d));
    float t2 = __fmul_rn(__fsub_rn(e, f), __fsub_rn(g, h));
    return __fsub_rn(t1, t2);
}

// One warp per (batch, triangle). Lanes split the 12x12 candidate window.
// Fixed-trip unrolled loop: 5 independent iterations, ILP + batched atomics.
__global__ void raster_kernel(const float* __restrict__ verts,
                              const int* __restrict__ faces) {
    int gw = (blockIdx.x * blockDim.x + threadIdx.x) >> 5;
    int lane = threadIdx.x & 31;
    if (gw >= NB * NF) return;
    int n = gw / NF;
    int f = gw - n * NF;

    int i0 = faces[3 * f + 0];
    int i1 = faces[3 * f + 1];
    int i2 = faces[3 * f + 2];
    const float* vb = verts + (size_t)n * NV * 3;

    float z0 = vb[3 * i0 + 2], z1 = vb[3 * i1 + 2], z2 = vb[3 * i2 + 2];
    // p = v * (1/z); rcp.rn is correctly rounded == div.rn(1,z) bitwise.
    float r0 = __frcp_rn(z0), r1 = __frcp_rn(z1), r2 = __frcp_rn(z2);
    float x0 = __fmul_rn(vb[3 * i0 + 0], r0), y0 = __fmul_rn(vb[3 * i0 + 1], r0);
    float x1 = __fmul_rn(vb[3 * i1 + 0], r1), y1 = __fmul_rn(vb[3 * i1 + 1], r1);
    float x2 = __fmul_rn(vb[3 * i2 + 0], r2), y2 = __fmul_rn(vb[3 * i2 + 1], r2);

    float area = edgefn(x1, x0, y2, y0, y1, y0, x2, x0);
    bool front = (z0 > 0.f) && (z1 > 0.f) && (z2 > 0.f);
    if (!front || !(fabsf(area) > 1e-9f)) return;
    float invA = __frcp_rn(area);

    float bminx = floorf(fminf(x0, fminf(x1, x2)));
    float bminy = floorf(fminf(y0, fminf(y1, y2)));
    int bcx = (int)fminf(fmaxf(bminx, 0.f), (float)(W_ - KK));
    int bcy = (int)fminf(fmaxf(bminy, 0.f), (float)(H_ - KK));

    unsigned long long* zb = g_zbuf + (size_t)n * HW;

    #pragma unroll 5
    for (int it = 0; it < 5; it++) {
        int t = lane + it * 32;
        if (t >= KK * KK) break;
        int oy = t / KK;          // const divisor -> mul/shift
        int ox = t - oy * KK;
        int px = bcx + ox;
        int py = bcy + oy;
        float pxf = (float)px, pyf = (float)py;
        float w0 = __fmul_rn(edgefn(x2, x1, pyf, y1, y2, y1, pxf, x1), invA);
        float w1 = __fmul_rn(edgefn(x0, x2, pyf, y2, y0, y2, pxf, x2), invA);
        float w2 = __fsub_rn(__fsub_rn(1.0f, w0), w1);
        if (w0 >= 0.f && w1 >= 0.f && w2 >= 0.f) {
            float depth = __fadd_rn(
                __fadd_rn(__fmul_rn(w0, z0), __fmul_rn(w1, z1)),
                __fmul_rn(w2, z2));
            // Same-pixel ties only arise between DIFFERENT triangles (each
            // window fragment of one triangle maps to a distinct pixel), so
            // packing f preserves the reference's (depth, m) tie-break.
            unsigned long long packed =
                ((unsigned long long)__float_as_uint(depth) << 32) |
                (unsigned int)f;
            atomicMax(zb + py * W_ + px, ~packed);   // max(~x) == ~min(x)
        }
    }
}

// One thread per (batch, pixel): decode winner face, recompute barycentrics
// with the SAME arithmetic, interpolate uv, apply epilogue, reset zbuf slot.
__global__ void shade_kernel(const float* __restrict__ verts,
                             const int* __restrict__ faces,
                             const float* __restrict__ vals,
                             float* __restrict__ out) {
    int gid = blockIdx.x * blockDim.x + threadIdx.x;
    if (gid >= NB * HW) return;
    int n = gid / HW;
    int pix = gid - n * HW;

    unsigned long long zv = g_zbuf[gid];
    g_zbuf[gid] = 0ull;   // reset for next replay (empty state == 0)

    float u = 0.f, v = 0.f;
    if (zv != 0ull) {
        int f = (int)(unsigned int)(~zv & 0xFFFFFFFFu);
        int i0 = faces[3 * f + 0];
        int i1 = faces[3 * f + 1];
        int i2 = faces[3 * f + 2];
        const float* vb = verts + (size_t)n * NV * 3;
        float z0 = vb[3 * i0 + 2], z1 = vb[3 * i1 + 2], z2 = vb[3 * i2 + 2];
        float r0 = __frcp_rn(z0), r1 = __frcp_rn(z1), r2 = __frcp_rn(z2);
        float x0 = __fmul_rn(vb[3 * i0 + 0], r0), y0 = __fmul_rn(vb[3 * i0 + 1], r0);
        float x1 = __fmul_rn(vb[3 * i1 + 0], r1), y1 = __fmul_rn(vb[3 * i1 + 1], r1);
        float x2 = __fmul_rn(vb[3 * i2 + 0], r2), y2 = __fmul_rn(vb[3 * i2 + 1], r2);
        float area = edgefn(x1, x0, y2, y0, y1, y0, x2, x0);
        float invA = __frcp_rn(area);
        int px = pix & (W_ - 1);
        int py = pix >> 9;
        float pxf = (float)px, pyf = (float)py;
        float w0 = __fmul_rn(edgefn(x2, x1, pyf, y1, y2, y1, pxf, x1), invA);
        float w1 = __fmul_rn(edgefn(x0, x2, pyf, y2, y0, y2, pxf, x2), invA);
        float w2 = __fsub_rn(__fsub_rn(1.0f, w0), w1);
        u = __fadd_rn(
            __fadd_rn(__fmul_rn(w0, vals[2 * i0 + 0]), __fmul_rn(w1, vals[2 * i1 + 0])),
            __fmul_rn(w2, vals[2 * i2 + 0]));
        v = __fadd_rn(
            __fadd_rn(__fmul_rn(w0, vals[2 * i0 + 1]), __fmul_rn(w1, vals[2 * i1 + 1])),
            __fmul_rn(w2, vals[2 * i2 + 1]));
    }
    float mask = (u > 0.f || v > 0.f) ? 1.f : 0.f;
    float ou, ov;
    if (mask > 0.f) {
        ou = __fsub_rn(__fmul_rn(2.f, u), 1.f);
        ov = __fsub_rn(__fmul_rn(2.f, v), 1.f);
    } else {
        ou = -10.f;
        ov = -10.f;
    }
    out[((size_t)n * 2 + 0) * HW + pix] = ou;
    out[((size_t)n * 2 + 1) * HW + pix] = ov;
    out[(size_t)NB * 2 * HW + (size_t)n * HW + pix] = mask;
}

extern "C" void kernel_launch(void* const* d_in, const int* in_sizes, int n_in,
                              void* d_out, int out_size) {
    const float* verts = (const float*)d_in[0];
    const int* faces = (const int*)d_in[1];
    const float* vals = (const float*)d_in[2];
    float* out = (float*)d_out;

    (void)in_sizes; (void)n_in; (void)out_size;

    int nwarps = NB * NF;                 // 107584 warps
    int rasterBlocks = (nwarps * 32 + 255) / 256;
    raster_kernel<<<rasterBlocks, 256>>>(verts, faces);

    int shadeBlocks = (NB * HW + 255) / 256;
    shade_kernel<<<shadeBlocks, 256>>>(verts, faces, vals, out);
}

// round 10
// speedup vs baseline: 1.5452x; 1.5027x over previous
#include <cuda_runtime.h>
#include <cstdint>

#define H_ 512
#define W_ 512
#define G_ 83
#define KK 12
#define NB 8
#define NV (G_ * G_)                 // 6889 vertices
#define NF (2 * (G_ - 1) * (G_ - 1)) // 13448 faces
#define HW (H_ * W_)

// 16 MB z-buffer scratch, re-initialized to all-ones each replay by init_kernel.
__device__ unsigned long long g_zbuf[NB * HW];

// Strict IEEE, non-fused edge function: (a-b)*(c-d) - (e-f)*(g-h)
__device__ __forceinline__ float edgefn(float a, float b, float c, float d,
                                        float e, float f, float g, float h) {
    float t1 = __fmul_rn(__fsub_rn(a, b), __fsub_rn(c, d));
    float t2 = __fmul_rn(__fsub_rn(e, f), __fsub_rn(g, h));
    return __fsub_rn(t1, t2);
}

// Vectorized 16B-store fill of the z-buffer sentinel.
__global__ void init_kernel() {
    int i = blockIdx.x * blockDim.x + threadIdx.x;
    ulonglong2 v = make_ulonglong2(0xFFFFFFFFFFFFFFFFull, 0xFFFFFFFFFFFFFFFFull);
    if (i < (NB * HW) / 2) reinterpret_cast<ulonglong2*>(g_zbuf)[i] = v;
}

// One warp per (batch, triangle). Lanes split the 12x12 candidate window.
// Fixed-trip unrolled loop (R5-proven): 5 independent iterations, ILP-rich.
__global__ void raster_kernel(const float* __restrict__ verts,
                              const int* __restrict__ faces) {
    int gw = (blockIdx.x * blockDim.x + threadIdx.x) >> 5;
    int lane = threadIdx.x & 31;
    if (gw >= NB * NF) return;
    int n = gw / NF;
    int f = gw - n * NF;

    int i0 = faces[3 * f + 0];
    int i1 = faces[3 * f + 1];
    int i2 = faces[3 * f + 2];
    const float* vb = verts + (size_t)n * NV * 3;

    float z0 = vb[3 * i0 + 2], z1 = vb[3 * i1 + 2], z2 = vb[3 * i2 + 2];
    // p = v * (1/z) with correctly-rounded reciprocal (XLA's div-by-broadcast
    // rewrite). __fdiv_rn(1,z) is the R5-proven lowering.
    float r0 = __fdiv_rn(1.0f, z0), r1 = __fdiv_rn(1.0f, z1), r2 = __fdiv_rn(1.0f, z2);
    float x0 = __fmul_rn(vb[3 * i0 + 0], r0), y0 = __fmul_rn(vb[3 * i0 + 1], r0);
    float x1 = __fmul_rn(vb[3 * i1 + 0], r1), y1 = __fmul_rn(vb[3 * i1 + 1], r1);
    float x2 = __fmul_rn(vb[3 * i2 + 0], r2), y2 = __fmul_rn(vb[3 * i2 + 1], r2);

    float area = edgefn(x1, x0, y2, y0, y1, y0, x2, x0);
    bool front = (z0 > 0.f) && (z1 > 0.f) && (z2 > 0.f);
    if (!front || !(fabsf(area) > 1e-9f)) return;
    float invA = __fdiv_rn(1.0f, area);

    float bminx = floorf(fminf(x0, fminf(x1, x2)));
    float bminy = floorf(fminf(y0, fminf(y1, y2)));
    int bcx = (int)fminf(fmaxf(bminx, 0.f), (float)(W_ - KK));
    int bcy = (int)fminf(fmaxf(bminy, 0.f), (float)(H_ - KK));

    unsigned long long* zb = g_zbuf + (size_t)n * HW;

    #pragma unroll 5
    for (int it = 0; it < 5; it++) {
        int t = lane + it * 32;
        if (t >= KK * KK) break;
        int oy = t / KK;          // const divisor -> mul/shift
        int ox = t - oy * KK;
        int px = bcx + ox;
        int py = bcy + oy;
        float pxf = (float)px, pyf = (float)py;
        float w0 = __fmul_rn(edgefn(x2, x1, pyf, y1, y2, y1, pxf, x1), invA);
        float w1 = __fmul_rn(edgefn(x0, x2, pyf, y2, y0, y2, pxf, x2), invA);
        float w2 = __fsub_rn(__fsub_rn(1.0f, w0), w1);
        if (w0 >= 0.f && w1 >= 0.f && w2 >= 0.f) {
            float depth = __fadd_rn(
                __fadd_rn(__fmul_rn(w0, z0), __fmul_rn(w1, z1)),
                __fmul_rn(w2, z2));
            // Same-pixel ties only arise between DIFFERENT triangles, so
            // packing f preserves the reference's (depth, m) tie-break.
            unsigned long long packed =
                ((unsigned long long)__float_as_uint(depth) << 32) |
                (unsigned int)f;
            atomicMin(zb + py * W_ + px, packed);
        }
    }
}

// One thread per (batch, pixel): decode winner face, recompute barycentrics
// with the SAME arithmetic, interpolate uv, apply epilogue, write uvs + mask.
__global__ void shade_kernel(const float* __restrict__ verts,
                             const int* __restrict__ faces,
                             const float* __restrict__ vals,
                             float* __restrict__ out) {
    int gid = blockIdx.x * blockDim.x + threadIdx.x;
    if (gid >= NB * HW) return;
    int n = gid / HW;
    int pix = gid - n * HW;

    unsigned long long zv = g_zbuf[gid];
    float u = 0.f, v = 0.f;
    if (zv != 0xFFFFFFFFFFFFFFFFull) {
        int f = (int)(unsigned int)(zv & 0xFFFFFFFFu);
        int i0 = faces[3 * f + 0];
        int i1 = faces[3 * f + 1];
        int i2 = faces[3 * f + 2];
        const float* vb = verts + (size_t)n * NV * 3;
        float z0 = vb[3 * i0 + 2], z1 = vb[3 * i1 + 2], z2 = vb[3 * i2 + 2];
        float r0 = __fdiv_rn(1.0f, z0), r1 = __fdiv_rn(1.0f, z1), r2 = __fdiv_rn(1.0f, z2);
        float x0 = __fmul_rn(vb[3 * i0 + 0], r0), y0 = __fmul_rn(vb[3 * i0 + 1], r0);
        float x1 = __fmul_rn(vb[3 * i1 + 0], r1), y1 = __fmul_rn(vb[3 * i1 + 1], r1);
        float x2 = __fmul_rn(vb[3 * i2 + 0], r2), y2 = __fmul_rn(vb[3 * i2 + 1], r2);
        float area = edgefn(x1, x0, y2, y0, y1, y0, x2, x0);
        float invA = __fdiv_rn(1.0f, area);
        int px = pix & (W_ - 1);
        int py = pix >> 9;
        float pxf = (float)px, pyf = (float)py;
        float w0 = __fmul_rn(edgefn(x2, x1, pyf, y1, y2, y1, pxf, x1), invA);
        float w1 = __fmul_rn(edgefn(x0, x2, pyf, y2, y0, y2, pxf, x2), invA);
        float w2 = __fsub_rn(__fsub_rn(1.0f, w0), w1);
        u = __fadd_rn(
            __fadd_rn(__fmul_rn(w0, vals[2 * i0 + 0]), __fmul_rn(w1, vals[2 * i1 + 0])),
            __fmul_rn(w2, vals[2 * i2 + 0]));
        v = __fadd_rn(
            __fadd_rn(__fmul_rn(w0, vals[2 * i0 + 1]), __fmul_rn(w1, vals[2 * i1 + 1])),
            __fmul_rn(w2, vals[2 * i2 + 1]));
    }
    float mask = (u > 0.f || v > 0.f) ? 1.f : 0.f;
    float ou, ov;
    if (mask > 0.f) {
        ou = __fsub_rn(__fmul_rn(2.f, u), 1.f);
        ov = __fsub_rn(__fmul_rn(2.f, v), 1.f);
    } else {
        ou = -10.f;
        ov = -10.f;
    }
    out[((size_t)n * 2 + 0) * HW + pix] = ou;
    out[((size_t)n * 2 + 1) * HW + pix] = ov;
    out[(size_t)NB * 2 * HW + (size_t)n * HW + pix] = mask;
}

extern "C" void kernel_launch(void* const* d_in, const int* in_sizes, int n_in,
                              void* d_out, int out_size) {
    const float* verts = (const float*)d_in[0];
    const int* faces = (const int*)d_in[1];
    const float* vals = (const float*)d_in[2];
    float* out = (float*)d_out;

    (void)in_sizes; (void)n_in; (void)out_size;

    int initBlocks = ((NB * HW) / 2 + 255) / 256;
    init_kernel<<<initBlocks, 256>>>();

    int nwarps = NB * NF;                 // 107584 warps
    int rasterBlocks = (nwarps * 32 + 255) / 256;
    raster_kernel<<<rasterBlocks, 256>>>(verts, faces);

    int shadeBlocks = (NB * HW + 255) / 256;
    shade_kernel<<<shadeBlocks, 256>>>(verts, faces, vals, out);
}

// round 11
// speedup vs baseline: 1.8158x; 1.1751x over previous
#include <cuda_runtime.h>
#include <cstdint>

#define H_ 512
#define W_ 512
#define G_ 83
#define KK 12
#define NB 8
#define NV (G_ * G_)                 // 6889 vertices
#define NF (2 * (G_ - 1) * (G_ - 1)) // 13448 faces
#define HW (H_ * W_)
#define NBNV (NB * NV)

// 16 MB z-buffer scratch, re-initialized each replay by prep_kernel.
__device__ unsigned long long g_zbuf[NB * HW];
// Precomputed projected vertices per (batch, vertex): (x, y, z, 0).
__device__ float4 g_pv[NBNV];
// Faces padded to int4 for single 128-bit loads.
__device__ int4 g_faces4[NF];

// Strict IEEE, non-fused edge function: (a-b)*(c-d) - (e-f)*(g-h)
__device__ __forceinline__ float edgefn(float a, float b, float c, float d,
                                        float e, float f, float g, float h) {
    float t1 = __fmul_rn(__fsub_rn(a, b), __fsub_rn(c, d));
    float t2 = __fmul_rn(__fsub_rn(e, f), __fsub_rn(g, h));
    return __fsub_rn(t1, t2);
}

// Combined prep: z-buffer fill (16B stores) + vertex projection + face pad.
// The 1M fill threads dominate; proj/face work rides along for free.
__global__ void prep_kernel(const float* __restrict__ verts,
                            const int* __restrict__ faces) {
    int i = blockIdx.x * blockDim.x + threadIdx.x;
    if (i < (NB * HW) / 2) {
        ulonglong2 s = make_ulonglong2(0xFFFFFFFFFFFFFFFFull,
                                       0xFFFFFFFFFFFFFFFFull);
        reinterpret_cast<ulonglong2*>(g_zbuf)[i] = s;
    }
    if (i < NBNV) {
        float vx = verts[3 * i + 0];
        float vy = verts[3 * i + 1];
        float vz = verts[3 * i + 2];
        // Same ops as before, merely hoisted: bit-identical projection.
        float r = __fdiv_rn(1.0f, vz);
        g_pv[i] = make_float4(__fmul_rn(vx, r), __fmul_rn(vy, r), vz, 0.0f);
    }
    if (i < NF) {
        g_faces4[i] = make_int4(faces[3 * i + 0], faces[3 * i + 1],
                                faces[3 * i + 2], 0);
    }
}

// One warp per (batch, triangle). Lanes split the 12x12 candidate window.
// Fixed-trip unrolled loop (proven): 5 independent iterations, ILP-rich.
__global__ void raster_kernel() {
    int gw = (blockIdx.x * blockDim.x + threadIdx.x) >> 5;
    int lane = threadIdx.x & 31;
    if (gw >= NB * NF) return;
    int n = gw / NF;
    int f = gw - n * NF;

    int4 fc = g_faces4[f];
    const float4* pv = g_pv + n * NV;
    float4 p0 = pv[fc.x];
    float4 p1 = pv[fc.y];
    float4 p2 = pv[fc.z];
    float x0 = p0.x, y0 = p0.y, z0 = p0.z;
    float x1 = p1.x, y1 = p1.y, z1 = p1.z;
    float x2 = p2.x, y2 = p2.y, z2 = p2.z;

    float area = edgefn(x1, x0, y2, y0, y1, y0, x2, x0);
    bool front = (z0 > 0.f) && (z1 > 0.f) && (z2 > 0.f);
    if (!front || !(fabsf(area) > 1e-9f)) return;
    float invA = __fdiv_rn(1.0f, area);

    float bminx = floorf(fminf(x0, fminf(x1, x2)));
    float bminy = floorf(fminf(y0, fminf(y1, y2)));
    int bcx = (int)fminf(fmaxf(bminx, 0.f), (float)(W_ - KK));
    int bcy = (int)fminf(fmaxf(bminy, 0.f), (float)(H_ - KK));

    unsigned long long* zb = g_zbuf + (size_t)n * HW;

    #pragma unroll 5
    for (int it = 0; it < 5; it++) {
        int t = lane + it * 32;
        if (t >= KK * KK) break;
        int oy = t / KK;          // const divisor -> mul/shift
        int ox = t - oy * KK;
        int px = bcx + ox;
        int py = bcy + oy;
        float pxf = (float)px, pyf = (float)py;
        float w0 = __fmul_rn(edgefn(x2, x1, pyf, y1, y2, y1, pxf, x1), invA);
        float w1 = __fmul_rn(edgefn(x0, x2, pyf, y2, y0, y2, pxf, x2), invA);
        float w2 = __fsub_rn(__fsub_rn(1.0f, w0), w1);
        if (w0 >= 0.f && w1 >= 0.f && w2 >= 0.f) {
            float depth = __fadd_rn(
                __fadd_rn(__fmul_rn(w0, z0), __fmul_rn(w1, z1)),
                __fmul_rn(w2, z2));
            // Same-pixel ties only arise between DIFFERENT triangles, so
            // packing f preserves the reference's (depth, m) tie-break.
            unsigned long long packed =
                ((unsigned long long)__float_as_uint(depth) << 32) |
                (unsigned int)f;
            atomicMin(zb + py * W_ + px, packed);
        }
    }
}

// One thread per (batch, pixel): decode winner face, recompute barycentrics
// from precomputed projections (same arithmetic), interpolate uv, epilogue.
__global__ void shade_kernel(const float* __restrict__ vals,
                             float* __restrict__ out) {
    int gid = blockIdx.x * blockDim.x + threadIdx.x;
    if (gid >= NB * HW) return;
    int n = gid / HW;
    int pix = gid - n * HW;

    unsigned long long zv = g_zbuf[gid];
    float u = 0.f, v = 0.f;
    if (zv != 0xFFFFFFFFFFFFFFFFull) {
        int f = (int)(unsigned int)(zv & 0xFFFFFFFFu);
        int4 fc = g_faces4[f];
        const float4* pv = g_pv + n * NV;
        float4 p0 = pv[fc.x];
        float4 p1 = pv[fc.y];
        float4 p2 = pv[fc.z];
        float x0 = p0.x, y0 = p0.y;
        float x1 = p1.x, y1 = p1.y;
        float x2 = p2.x, y2 = p2.y;
        float area = edgefn(x1, x0, y2, y0, y1, y0, x2, x0);
        float invA = __fdiv_rn(1.0f, area);
        int px = pix & (W_ - 1);
        int py = pix >> 9;
        float pxf = (float)px, pyf = (float)py;
        float w0 = __fmul_rn(edgefn(x2, x1, pyf, y1, y2, y1, pxf, x1), invA);
        float w1 = __fmul_rn(edgefn(x0, x2, pyf, y2, y0, y2, pxf, x2), invA);
        float w2 = __fsub_rn(__fsub_rn(1.0f, w0), w1);
        const float2* vl = reinterpret_cast<const float2*>(vals);
        float2 va = vl[fc.x];
        float2 vbv = vl[fc.y];
        float2 vc = vl[fc.z];
        u = __fadd_rn(
            __fadd_rn(__fmul_rn(w0, va.x), __fmul_rn(w1, vbv.x)),
            __fmul_rn(w2, vc.x));
        v = __fadd_rn(
            __fadd_rn(__fmul_rn(w0, va.y), __fmul_rn(w1, vbv.y)),
            __fmul_rn(w2, vc.y));
    }
    float mask = (u > 0.f || v > 0.f) ? 1.f : 0.f;
    float ou, ov;
    if (mask > 0.f) {
        ou = __fsub_rn(__fmul_rn(2.f, u), 1.f);
        ov = __fsub_rn(__fmul_rn(2.f, v), 1.f);
    } else {
        ou = -10.f;
        ov = -10.f;
    }
    out[((size_t)n * 2 + 0) * HW + pix] = ou;
    out[((size_t)n * 2 + 1) * HW + pix] = ov;
    out[(size_t)NB * 2 * HW + (size_t)n * HW + pix] = mask;
}

extern "C" void kernel_launch(void* const* d_in, const int* in_sizes, int n_in,
                              void* d_out, int out_size) {
    const float* verts = (const float*)d_in[0];
    const int* faces = (const int*)d_in[1];
    const float* vals = (const float*)d_in[2];
    float* out = (float*)d_out;

    (void)in_sizes; (void)n_in; (void)out_size;

    int prepBlocks = ((NB * HW) / 2 + 255) / 256;   // covers fill, proj, faces
    prep_kernel<<<prepBlocks, 256>>>(verts, faces);

    int nwarps = NB * NF;                 // 107584 warps
    int rasterBlocks = (nwarps * 32 + 255) / 256;
    raster_kernel<<<rasterBlocks, 256>>>();

    int shadeBlocks = (NB * HW + 255) / 256;
    shade_kernel<<<shadeBlocks, 256>>>(vals, out);
}

// round 12
// speedup vs baseline: 2.2278x; 1.2269x over previous
#include <cuda_runtime.h>
#include <cstdint>

#define H_ 512
#define W_ 512
#define G_ 83
#define KK 12
#define NB 8
#define NV (G_ * G_)                 // 6889 vertices
#define NF (2 * (G_ - 1) * (G_ - 1)) // 13448 faces
#define HW (H_ * W_)
#define NBNV (NB * NV)
#define NTRI (NB * NF)               // 107584 (even)

// 16 MB z-buffer scratch, re-initialized each replay by prep_kernel.
__device__ unsigned long long g_zbuf[NB * HW];
// Precomputed projected vertices per (batch, vertex): (x, y, z, 0).
__device__ float4 g_pv[NBNV];
// Faces padded to int4 for single 128-bit loads.
__device__ int4 g_faces4[NF];

// Strict IEEE, non-fused edge function: (a-b)*(c-d) - (e-f)*(g-h)
__device__ __forceinline__ float edgefn(float a, float b, float c, float d,
                                        float e, float f, float g, float h) {
    float t1 = __fmul_rn(__fsub_rn(a, b), __fsub_rn(c, d));
    float t2 = __fmul_rn(__fsub_rn(e, f), __fsub_rn(g, h));
    return __fsub_rn(t1, t2);
}

// Combined prep: z-buffer fill (16B stores) + vertex projection + face pad.
__global__ void prep_kernel(const float* __restrict__ verts,
                            const int* __restrict__ faces) {
    int i = blockIdx.x * blockDim.x + threadIdx.x;
    if (i < (NB * HW) / 2) {
        ulonglong2 s = make_ulonglong2(0xFFFFFFFFFFFFFFFFull,
                                       0xFFFFFFFFFFFFFFFFull);
        reinterpret_cast<ulonglong2*>(g_zbuf)[i] = s;
    }
    if (i < NBNV) {
        float vx = verts[3 * i + 0];
        float vy = verts[3 * i + 1];
        float vz = verts[3 * i + 2];
        float r = __fdiv_rn(1.0f, vz);   // bit-identical hoisted projection
        g_pv[i] = make_float4(__fmul_rn(vx, r), __fmul_rn(vy, r), vz, 0.0f);
    }
    if (i < NF) {
        g_faces4[i] = make_int4(faces[3 * i + 0], faces[3 * i + 1],
                                faces[3 * i + 2], 0);
    }
}

// TWO triangles per warp: lanes 0-15 -> tri 2*gw, lanes 16-31 -> tri 2*gw+1.
// Each 16-lane half iterates a COMPACT bbox-clipped candidate set.
// Excluded pixels are >= 1 px outside the vertex extent: some barycentric is
// <= -1/12 in exact arithmetic, so fp noise cannot make the reference's
// w>=0 test pass there. Identical arithmetic + (depth, f) key elsewhere.
__global__ void raster_kernel() {
    int gw = (blockIdx.x * blockDim.x + threadIdx.x) >> 5;
    int lane = threadIdx.x & 31;
    if (gw >= NTRI / 2) return;
    int sub = lane & 15;
    int tri = gw * 2 + (lane >> 4);
    int n = tri / NF;
    int f = tri - n * NF;

    int4 fc = g_faces4[f];
    const float4* pv = g_pv + n * NV;
    float4 p0 = pv[fc.x];
    float4 p1 = pv[fc.y];
    float4 p2 = pv[fc.z];
    float x0 = p0.x, y0 = p0.y, z0 = p0.z;
    float x1 = p1.x, y1 = p1.y, z1 = p1.z;
    float x2 = p2.x, y2 = p2.y, z2 = p2.z;

    float area = edgefn(x1, x0, y2, y0, y1, y0, x2, x0);
    bool ok = (z0 > 0.f) && (z1 > 0.f) && (z2 > 0.f) && (fabsf(area) > 1e-9f);
    float invA = __fdiv_rn(1.0f, area);

    float xmn = fminf(x0, fminf(x1, x2));
    float xmx = fmaxf(x0, fmaxf(x1, x2));
    float ymn = fminf(y0, fminf(y1, y2));
    float ymx = fmaxf(y0, fmaxf(y1, y2));
    int fxmn = (int)floorf(xmn);
    int fymn = (int)floorf(ymn);
    int bcx = min(max(fxmn, 0), W_ - KK);
    int bcy = min(max(fymn, 0), H_ - KK);

    int xlo = max(bcx, fxmn);
    int xhi = min(bcx + KK - 1, (int)ceilf(xmx));
    int ylo = max(bcy, fymn);
    int yhi = min(bcy + KK - 1, (int)ceilf(ymx));
    int bw = xhi - xlo + 1;
    int bh = yhi - ylo + 1;
    int cnt = (ok && bw > 0 && bh > 0) ? bw * bh : 0;
    // Exact division t/bw for t < 2^16 via magic multiply.
    unsigned magic = (65536u + (unsigned)bw - 1) / (unsigned)max(bw, 1);

    unsigned long long* zb = g_zbuf + (size_t)n * HW;

    for (int t = sub; t < cnt; t += 16) {
        int oy = (int)(((unsigned)t * magic) >> 16);
        int ox = t - oy * bw;
        int px = xlo + ox;
        int py = ylo + oy;
        float pxf = (float)px, pyf = (float)py;
        float w0 = __fmul_rn(edgefn(x2, x1, pyf, y1, y2, y1, pxf, x1), invA);
        float w1 = __fmul_rn(edgefn(x0, x2, pyf, y2, y0, y2, pxf, x2), invA);
        float w2 = __fsub_rn(__fsub_rn(1.0f, w0), w1);
        if (w0 >= 0.f && w1 >= 0.f && w2 >= 0.f) {
            float depth = __fadd_rn(
                __fadd_rn(__fmul_rn(w0, z0), __fmul_rn(w1, z1)),
                __fmul_rn(w2, z2));
            // Same-pixel ties only arise between DIFFERENT triangles, so
            // packing f preserves the reference's (depth, m) tie-break.
            unsigned long long packed =
                ((unsigned long long)__float_as_uint(depth) << 32) |
                (unsigned int)f;
            atomicMin(zb + py * W_ + px, packed);
        }
    }
}

// One thread per (batch, pixel): decode winner face, recompute barycentrics
// from precomputed projections (same arithmetic), interpolate uv, epilogue.
__global__ void shade_kernel(const float* __restrict__ vals,
                             float* __restrict__ out) {
    int gid = blockIdx.x * blockDim.x + threadIdx.x;
    if (gid >= NB * HW) return;
    int n = gid / HW;
    int pix = gid - n * HW;

    unsigned long long zv = g_zbuf[gid];
    float u = 0.f, v = 0.f;
    if (zv != 0xFFFFFFFFFFFFFFFFull) {
        int f = (int)(unsigned int)(zv & 0xFFFFFFFFu);
        int4 fc = g_faces4[f];
        const float4* pv = g_pv + n * NV;
        float4 p0 = pv[fc.x];
        float4 p1 = pv[fc.y];
        float4 p2 = pv[fc.z];
        float x0 = p0.x, y0 = p0.y;
        float x1 = p1.x, y1 = p1.y;
        float x2 = p2.x, y2 = p2.y;
        float area = edgefn(x1, x0, y2, y0, y1, y0, x2, x0);
        float invA = __fdiv_rn(1.0f, area);
        int px = pix & (W_ - 1);
        int py = pix >> 9;
        float pxf = (float)px, pyf = (float)py;
        float w0 = __fmul_rn(edgefn(x2, x1, pyf, y1, y2, y1, pxf, x1), invA);
        float w1 = __fmul_rn(edgefn(x0, x2, pyf, y2, y0, y2, pxf, x2), invA);
        float w2 = __fsub_rn(__fsub_rn(1.0f, w0), w1);
        const float2* vl = reinterpret_cast<const float2*>(vals);
        float2 va = vl[fc.x];
        float2 vbv = vl[fc.y];
        float2 vc = vl[fc.z];
        u = __fadd_rn(
            __fadd_rn(__fmul_rn(w0, va.x), __fmul_rn(w1, vbv.x)),
            __fmul_rn(w2, vc.x));
        v = __fadd_rn(
            __fadd_rn(__fmul_rn(w0, va.y), __fmul_rn(w1, vbv.y)),
            __fmul_rn(w2, vc.y));
    }
    float mask = (u > 0.f || v > 0.f) ? 1.f : 0.f;
    float ou, ov;
    if (mask > 0.f) {
        ou = __fsub_rn(__fmul_rn(2.f, u), 1.f);
        ov = __fsub_rn(__fmul_rn(2.f, v), 1.f);
    } else {
        ou = -10.f;
        ov = -10.f;
    }
    out[((size_t)n * 2 + 0) * HW + pix] = ou;
    out[((size_t)n * 2 + 1) * HW + pix] = ov;
    out[(size_t)NB * 2 * HW + (size_t)n * HW + pix] = mask;
}

extern "C" void kernel_launch(void* const* d_in, const int* in_sizes, int n_in,
                              void* d_out, int out_size) {
    const float* verts = (const float*)d_in[0];
    const int* faces = (const int*)d_in[1];
    const float* vals = (const float*)d_in[2];
    float* out = (float*)d_out;

    (void)in_sizes; (void)n_in; (void)out_size;

    int prepBlocks = ((NB * HW) / 2 + 255) / 256;   // covers fill, proj, faces
    prep_kernel<<<prepBlocks, 256>>>(verts, faces);

    int nwarps = NTRI / 2;                 // 53792 warps, 2 tri each
    int rasterBlocks = (nwarps * 32 + 255) / 256;
    raster_kernel<<<rasterBlocks, 256>>>();

    int shadeBlocks = (NB * HW + 255) / 256;
    shade_kernel<<<shadeBlocks, 256>>>(vals, out);
}